// round 4
// baseline (speedup 1.0000x reference)
#include <cuda_runtime.h>
#include <math_constants.h>

// Quantize (VQ-VAE) for GB300 — Round 2: packed fma.rn.f32x2 inner loop.
//   inputs:       (8,64,32,128) f32  -> 16384 samples x 128 dims
//   cluster_mean: (128,10000)   f32  -> codebook, d-major
//   out: 2097152 f32 outputs (straight-through) + 1 f32 loss
//
// argmin over (||c||^2 - 2 x.c), full fp32 FMA rounding (bit-identical to
// scalar FFMA version; f32x2 is two independent fp32 FMAs per instruction).

#define NS    16384
#define DD    128
#define NC    10000
#define TM    128
#define TN    128
#define NT    ((NC + TN - 1) / TN)   // 79
#define NOUT  (NS * DD)
#define NBLK  (NOUT / 256)

// Xs duplicated (each x stored twice for splat-free f32x2 A operand):
//   Xs_dup: 128 d x 256 f32 = 131072 B ; Cs: 128 x 128 f32 = 65536 B ; Ns: 512 B
#define SMEM_BYTES ((TM * DD * 2 + TN * DD + TN) * 4)   // 197120 B

__device__ float  g_norms[NC];
__device__ int    g_idx[NS];
__device__ double g_partial[NBLK];

typedef unsigned long long u64;

__device__ __forceinline__ void ffma2(u64& d, u64 a, u64 b) {
    asm("fma.rn.f32x2 %0, %1, %2, %0;" : "+l"(d) : "l"(a), "l"(b));
}
__device__ __forceinline__ void unpack2(float& lo, float& hi, u64 v) {
    asm("mov.b64 {%0, %1}, %2;" : "=f"(lo), "=f"(hi) : "l"(v));
}

// ---------------------------------------------------------------- code norms
__global__ void k_norms(const float* __restrict__ C) {
    int j = blockIdx.x * 256 + threadIdx.x;
    if (j >= NC) return;
    float s = 0.f;
#pragma unroll 8
    for (int d = 0; d < DD; d++) {
        float v = C[(size_t)d * NC + j];
        s = fmaf(v, v, s);
    }
    g_norms[j] = s;
}

// ------------------------------------------------- fused GEMM + argmin kernel
// 128 CTAs x 256 threads (16x16). Thread micro-tile: rows {ty*4..+3, 64+ty*4..+3},
// cols {tx*4..+3, 64+tx*4..+3}. Accumulators packed along columns (f32x2).
__global__ __launch_bounds__(256, 1)
void k_argmin(const float* __restrict__ X, const float* __restrict__ C) {
    extern __shared__ float smem[];
    float* Xs = smem;                      // dup layout: [d][2*i + {0,1}] both = x
    float* Cs = smem + TM * DD * 2;        // [d][j]
    float* Ns = smem + TM * DD * 2 + TN * DD;

    const int tid = threadIdx.x;
    const int tx = tid & 15;
    const int ty = tid >> 4;
    const int sbase = blockIdx.x * TM;

    // Load X tile, transposed + duplicated: X[(sbase+i)*128+d] -> Xs[d*256 + 2i(+1)]
    for (int r = tid; r < TM * DD / 4; r += 256) {
        int i  = r >> 5;
        int d4 = (r & 31) << 2;
        float4 v = *(const float4*)(X + (size_t)(sbase + i) * DD + d4);
        float* p0 = Xs + (d4 + 0) * (2 * TM) + 2 * i;
        float* p1 = Xs + (d4 + 1) * (2 * TM) + 2 * i;
        float* p2 = Xs + (d4 + 2) * (2 * TM) + 2 * i;
        float* p3 = Xs + (d4 + 3) * (2 * TM) + 2 * i;
        p0[0] = v.x; p0[1] = v.x;
        p1[0] = v.y; p1[1] = v.y;
        p2[0] = v.z; p2[1] = v.z;
        p3[0] = v.w; p3[1] = v.w;
    }

    float minv[8];
    int   mini[8];
#pragma unroll
    for (int r = 0; r < 8; r++) { minv[r] = CUDART_INF_F; mini[r] = 0; }

    const u64* Xs2 = (const u64*)Xs;   // [d][128] : entry i = (x_i, x_i)
    const u64* Cs2 = (const u64*)Cs;   // [d][64]  : entry u = (c_{2u}, c_{2u+1})

    for (int t = 0; t < NT; t++) {
        const int jbase = t * TN;
        __syncthreads();

        if (jbase + TN <= NC) {
#pragma unroll 4
            for (int r = tid; r < TN * DD / 4; r += 256) {
                int d  = r >> 5;
                int j4 = (r & 31) << 2;
                *(float4*)(Cs + d * TN + j4) =
                    *(const float4*)(C + (size_t)d * NC + jbase + j4);
            }
        } else {
            for (int r = tid; r < TN * DD; r += 256) {
                int d = r >> 7;
                int j = r & 127;
                int jj = jbase + j;
                Cs[d * TN + j] = (jj < NC) ? C[(size_t)d * NC + jj] : 0.f;
            }
        }
        if (tid < TN) {
            int jj = jbase + tid;
            Ns[tid] = (jj < NC) ? g_norms[jj] : CUDART_INF_F;
        }
        __syncthreads();

        u64 acc[8][4];
#pragma unroll
        for (int r = 0; r < 8; r++)
#pragma unroll
            for (int c = 0; c < 4; c++) acc[r][c] = 0ull;

#pragma unroll 4
        for (int d = 0; d < DD; d++) {
            const u64* xr = Xs2 + d * TM;        // 128 u64 per row
            const u64* cr = Cs2 + d * (TN / 2);  // 64 u64 per row
            u64 a[8], b[4];
#pragma unroll
            for (int r = 0; r < 4; r++) {
                a[r]     = xr[(ty << 2) + r];
                a[4 + r] = xr[64 + (ty << 2) + r];
            }
            b[0] = cr[(tx << 1)];
            b[1] = cr[(tx << 1) + 1];
            b[2] = cr[32 + (tx << 1)];
            b[3] = cr[32 + (tx << 1) + 1];
#pragma unroll
            for (int r = 0; r < 8; r++)
#pragma unroll
                for (int c = 0; c < 4; c++)
                    ffma2(acc[r][c], a[r], b[c]);
        }

        // Epilogue: dist = n_j - 2*dot ; strict < keeps first index on ties.
#pragma unroll
        for (int c = 0; c < 4; c++) {
            int j0 = (c < 2) ? ((tx << 2) + 2 * c) : (64 + (tx << 2) + 2 * (c - 2));
            float n0 = Ns[j0], n1 = Ns[j0 + 1];
            int jj0 = jbase + j0;
#pragma unroll
            for (int r = 0; r < 8; r++) {
                float lo, hi;
                unpack2(lo, hi, acc[r][c]);
                float v0 = fmaf(-2.f, lo, n0);
                float v1 = fmaf(-2.f, hi, n1);
                if (v0 < minv[r]) { minv[r] = v0; mini[r] = jj0; }
                if (v1 < minv[r]) { minv[r] = v1; mini[r] = jj0 + 1; }
            }
        }
    }

    // Cross-thread argmin reduction (16 tx candidates per sample row).
    __syncthreads();
    float* redv = Cs;                  // 2048 floats
    int*   redi = (int*)(Cs + 2048);   // 2048 ints
#pragma unroll
    for (int r = 0; r < 8; r++) {
        int i = (r < 4) ? ((ty << 2) + r) : (64 + (ty << 2) + (r - 4));
        redv[i * 16 + tx] = minv[r];
        redi[i * 16 + tx] = mini[r];
    }
    __syncthreads();
    if (tid < TM) {
        float bv = redv[tid * 16];
        int   bi = redi[tid * 16];
#pragma unroll
        for (int u = 1; u < 16; u++) {
            float v  = redv[tid * 16 + u];
            int   ix = redi[tid * 16 + u];
            if (v < bv || (v == bv && ix < bi)) { bv = v; bi = ix; }
        }
        g_idx[sbase + tid] = bi;
    }
}

// ------------------------------------- gather + straight-through + loss parts
__global__ void k_gather(const float* __restrict__ X, const float* __restrict__ C,
                         float* __restrict__ out) {
    int t = blockIdx.x * 256 + threadIdx.x;
    int i = t >> 7;
    int d = t & 127;
    int j = g_idx[i];
    float x = X[t];
    float q = C[(size_t)d * NC + j];
    out[t] = x + (q - x);
    float diff = q - x;
    float v = diff * diff;
#pragma unroll
    for (int off = 16; off > 0; off >>= 1)
        v += __shfl_down_sync(0xffffffffu, v, off);
    __shared__ float ws[8];
    int lane = threadIdx.x & 31, w = threadIdx.x >> 5;
    if (lane == 0) ws[w] = v;
    __syncthreads();
    if (threadIdx.x == 0) {
        double s = 0.0;
        for (int k = 0; k < 8; k++) s += (double)ws[k];
        g_partial[blockIdx.x] = s;
    }
}

// --------------------------------------------------- final deterministic loss
__global__ void k_loss(float* __restrict__ out, int loss_pos) {
    __shared__ double sm[256];
    double s = 0.0;
    for (int k = threadIdx.x; k < NBLK; k += 256) s += g_partial[k];
    sm[threadIdx.x] = s;
    __syncthreads();
    for (int off = 128; off > 0; off >>= 1) {
        if (threadIdx.x < off) sm[threadIdx.x] += sm[threadIdx.x + off];
        __syncthreads();
    }
    if (threadIdx.x == 0 && loss_pos >= 0)
        out[loss_pos] = (float)(1.25 * sm[0] / (double)NOUT);
}

// ---------------------------------------------------------------------- entry
extern "C" void kernel_launch(void* const* d_in, const int* in_sizes, int n_in,
                              void* d_out, int out_size) {
    const float* X = (const float*)d_in[0];
    const float* C = (const float*)d_in[1];
    if (n_in >= 2 && in_sizes[0] == DD * NC && in_sizes[1] == NOUT) {
        const float* tmp = X; X = C; C = tmp;
    }
    float* out = (float*)d_out;

    cudaFuncSetAttribute(k_argmin, cudaFuncAttributeMaxDynamicSharedMemorySize,
                         SMEM_BYTES);

    k_norms<<<(NC + 255) / 256, 256>>>(C);
    k_argmin<<<NS / TM, 256, SMEM_BYTES>>>(X, C);
    k_gather<<<NBLK, 256>>>(X, C, out);

    int loss_pos = (out_size > NOUT) ? (out_size - 1) : -1;
    k_loss<<<1, 256>>>(out, loss_pos);
}

// round 6
// speedup vs baseline: 1.0343x; 1.0343x over previous
#include <cuda_runtime.h>
#include <cuda_fp16.h>
#include <math_constants.h>
#include <cstdint>

// VQ-VAE Quantize on GB300 — Round 5: legacy mma.sync (m16n8k16 fp16, fp32 acc),
// 3-term fp16 split GEMM + top-2 margin tracking + exact fp32 rescue.
//   dist_j = ||c_j||^2 - 2 x.c_j ; argmin_j ; gather + straight-through + loss.

#define NS    16384
#define DD    128
#define NC    10000
#define NT    79               // N tiles of 128 (padded to 10112)
#define KE    384              // 3 terms x 128
#define PADK  392              // padded K row (fp16 elems) -> 784 B rows
#define ROWB  784
#define NOUT  (NS * DD)
#define NBLK  (NOUT / 256)
#define MARGIN 0.02f

#define A_BYTES  (128 * ROWB)      // 100352
#define BH_BYTES (64 * ROWB)       // 50176 (half tile: 64 codes)
#define SM_A   0
#define SM_B0  A_BYTES
#define SM_B1  (A_BYTES + BH_BYTES)
#define SM_MB  (A_BYTES + 2 * BH_BYTES)
#define SM_SZ  (SM_MB + 48)
#define SMEM_REQ (SM_SZ + 1024)

__device__ __half  g_Xe[(size_t)NS * PADK];         // A_ext tiles [s][PADK]
__device__ __half  g_Be[(size_t)NT * 128 * PADK];   // B_ext tiles [J][PADK]
__device__ float   g_norms[NT * 128];               // exact ||c||^2 (+INF pads)
__device__ int     g_idx[NS];
__device__ int     g_flag[NS];
__device__ int     g_nflag;
__device__ double  g_partial[NBLK];

// ------------------------------------------------------------------ helpers
__device__ __forceinline__ uint32_t smem_u32(const void* p) {
    uint32_t a;
    asm("{ .reg .u64 t; cvta.to.shared.u64 t, %1; cvt.u32.u64 %0, t; }" : "=r"(a) : "l"(p));
    return a;
}
__device__ __forceinline__ void mbar_init(uint32_t mbar, uint32_t cnt) {
    asm volatile("mbarrier.init.shared.b64 [%0], %1;" :: "r"(mbar), "r"(cnt) : "memory");
}
__device__ __forceinline__ void mbar_expect_tx(uint32_t mbar, uint32_t bytes) {
    asm volatile("mbarrier.arrive.expect_tx.shared.b64 _, [%0], %1;"
                 :: "r"(mbar), "r"(bytes) : "memory");
}
__device__ __forceinline__ void mbar_arrive(uint32_t mbar) {
    asm volatile("mbarrier.arrive.shared.b64 _, [%0];" :: "r"(mbar) : "memory");
}
__device__ __forceinline__ void mbar_wait(uint32_t mbar, uint32_t parity) {
    asm volatile(
        "{\n\t.reg .pred P;\n"
        "W%=:\n\t"
        "mbarrier.try_wait.parity.acquire.cta.shared::cta.b64 P, [%0], %1, 0x989680;\n\t"
        "@P bra D%=;\n\t"
        "bra W%=;\n"
        "D%=:\n\t}"
        :: "r"(mbar), "r"(parity) : "memory");
}
__device__ __forceinline__ void bulk_g2s(uint32_t dst, const void* src, uint32_t bytes,
                                         uint32_t mbar) {
    asm volatile(
        "cp.async.bulk.shared::cluster.global.mbarrier::complete_tx::bytes [%0], [%1], %2, [%3];"
        :: "r"(dst), "l"(src), "r"(bytes), "r"(mbar) : "memory");
}
__device__ __forceinline__ void ldsm4(uint32_t& r0, uint32_t& r1, uint32_t& r2, uint32_t& r3,
                                      uint32_t addr) {
    asm volatile("ldmatrix.sync.aligned.m8n8.x4.shared.b16 {%0,%1,%2,%3}, [%4];"
                 : "=r"(r0), "=r"(r1), "=r"(r2), "=r"(r3) : "r"(addr));
}
__device__ __forceinline__ void mma16816(float& d0, float& d1, float& d2, float& d3,
                                         uint32_t a0, uint32_t a1, uint32_t a2, uint32_t a3,
                                         uint32_t b0, uint32_t b1) {
    asm volatile(
        "mma.sync.aligned.m16n8k16.row.col.f32.f16.f16.f32 "
        "{%0,%1,%2,%3}, {%4,%5,%6,%7}, {%8,%9}, {%0,%1,%2,%3};"
        : "+f"(d0), "+f"(d1), "+f"(d2), "+f"(d3)
        : "r"(a0), "r"(a1), "r"(a2), "r"(a3), "r"(b0), "r"(b1));
}

// ------------------------------------------------------------ pre-processing
__global__ void k_norms(const float* __restrict__ C) {
    int j = blockIdx.x * 256 + threadIdx.x;
    if (j >= NT * 128) return;
    if (j >= NC) { g_norms[j] = CUDART_INF_F; return; }
    float s = 0.f;
#pragma unroll 8
    for (int d = 0; d < DD; d++) {
        float v = C[(size_t)d * NC + j];
        s = fmaf(v, v, s);
    }
    g_norms[j] = s;
}

// A_ext = [x_hi | x_hi | x_lo]  (fp16), padded rows of PADK
__global__ void k_prep_x(const float* __restrict__ X) {
    int id = blockIdx.x * 256 + threadIdx.x;     // s*128 + d
    if (id == 0) g_nflag = 0;                    // reset rescue counter each replay
    int s = id >> 7, d = id & 127;
    float  x  = X[id];
    __half h  = __float2half_rn(x);
    __half l  = __float2half_rn(x - __half2float(h));
    size_t base = (size_t)s * PADK;
    g_Xe[base + d]       = h;
    g_Xe[base + 128 + d] = h;
    g_Xe[base + 256 + d] = l;
}

// B_ext = [c_hi | c_lo | c_hi]  (fp16), rows J (code index, padded to 10112)
__global__ void k_prep_c(const float* __restrict__ C) {
    int id = blockIdx.x * 256 + threadIdx.x;     // J*128 + d
    if (id >= NT * 128 * 128) return;
    int J = id >> 7, d = id & 127;
    float c = (J < NC) ? C[(size_t)d * NC + J] : 0.f;
    __half h = __float2half_rn(c);
    __half l = __float2half_rn(c - __half2float(h));
    size_t base = (size_t)J * PADK;
    g_Be[base + d]       = h;
    g_Be[base + 128 + d] = l;
    g_Be[base + 256 + d] = h;
}

// --------------------------------------------------- main tensor-core kernel
// 128 CTAs x 288 threads. Warps 0-7 (4x2 grid over m64? -> wm 0..3 x wn 0..1,
// warp tile 32x32): mma consumers. Warp 8 thread 256: B producer.
__global__ __launch_bounds__(288, 1)
void k_argmin(void) {
    extern __shared__ char sraw[];
    const uint32_t sb0 = smem_u32(sraw);
    const uint32_t sb  = (sb0 + 1023u) & ~1023u;
    char* s0 = sraw + (sb - sb0);
    const int tid = threadIdx.x;

    const uint32_t mbF0 = sb + SM_MB + 0;
    const uint32_t mbF1 = sb + SM_MB + 8;
    const uint32_t mbE0 = sb + SM_MB + 16;
    const uint32_t mbE1 = sb + SM_MB + 24;
    const uint32_t mbA  = sb + SM_MB + 32;

    if (tid == 0) {
        mbar_init(mbF0, 1); mbar_init(mbF1, 1);
        mbar_init(mbE0, 1); mbar_init(mbE1, 1); mbar_init(mbA, 1);
    }
    __syncthreads();

    if (tid == 256) {
        // ----------------------------- producer -----------------------------
        mbar_expect_tx(mbA, A_BYTES);
        bulk_g2s(sb + SM_A, (const char*)g_Xe + (size_t)blockIdx.x * A_BYTES,
                 A_BYTES, mbA);
        const char* be = (const char*)g_Be;
        for (int h = 0; h < 2 * NT; h++) {
            int buf = h & 1, ph = (h >> 1) & 1;
            mbar_wait(buf ? mbE1 : mbE0, ph ^ 1);   // first pass-through free
            uint32_t mf = buf ? mbF1 : mbF0;
            mbar_expect_tx(mf, BH_BYTES);
            bulk_g2s(sb + (buf ? SM_B1 : SM_B0),
                     be + (size_t)(h >> 1) * (128 * ROWB) + (size_t)buf * BH_BYTES,
                     BH_BYTES, mf);
        }
    } else if (tid < 256) {
        // ----------------------------- consumers ----------------------------
        const int l  = tid & 31;
        const int wid = tid >> 5;
        const int wm = wid & 3;        // m in [wm*32, wm*32+32)
        const int wn = wid >> 2;       // n in [wn*32, wn*32+32) within 64-half

        // ldmatrix lane addresses
        const uint32_t rowA  = (uint32_t)(wm * 32 + ((l >> 3) & 1) * 8 + (l & 7));
        const uint32_t aoff  = (uint32_t)(((l >> 4) & 1) * 16);
        const uint32_t addrA = sb + SM_A + rowA * ROWB + aoff;
        const uint32_t rowBl = (uint32_t)(wn * 32 + ((l >> 4) & 1) * 8 + (l & 7));
        const uint32_t boff  = (uint32_t)(((l >> 3) & 1) * 16);

        float v1[4], v2[4]; int i1[4];
#pragma unroll
        for (int r = 0; r < 4; r++) { v1[r] = CUDART_INF_F; v2[r] = CUDART_INF_F; i1[r] = 0; }

        mbar_wait(mbA, 0);

        for (int h = 0; h < 2 * NT; h++) {
            const int buf = h & 1, ph = (h >> 1) & 1;
            const int tile = h >> 1, hb = h & 1;
            const uint32_t bbase = sb + (buf ? SM_B1 : SM_B0);
            mbar_wait(buf ? mbF1 : mbF0, ph);

            float acc[2][4][4];
#pragma unroll
            for (int sm = 0; sm < 2; sm++)
#pragma unroll
                for (int sn = 0; sn < 4; sn++)
#pragma unroll
                    for (int q = 0; q < 4; q++) acc[sm][sn][q] = 0.f;

            const uint32_t aA0 = addrA;
            const uint32_t aA1 = addrA + 16 * ROWB;
            const uint32_t aB0 = bbase + rowBl * ROWB + boff;
            const uint32_t aB1 = aB0 + 16 * ROWB;

#pragma unroll
            for (int ks = 0; ks < 24; ks++) {
                const uint32_t ko = (uint32_t)(ks * 32);
                uint32_t af0[4], af1[4], bf0[4], bf1[4];
                ldsm4(af0[0], af0[1], af0[2], af0[3], aA0 + ko);
                ldsm4(af1[0], af1[1], af1[2], af1[3], aA1 + ko);
                ldsm4(bf0[0], bf0[1], bf0[2], bf0[3], aB0 + ko);
                ldsm4(bf1[0], bf1[1], bf1[2], bf1[3], aB1 + ko);
                // sn0={bf0[0],bf0[1]} sn1={bf0[2],bf0[3]} sn2/3 from bf1
                mma16816(acc[0][0][0], acc[0][0][1], acc[0][0][2], acc[0][0][3],
                         af0[0], af0[1], af0[2], af0[3], bf0[0], bf0[1]);
                mma16816(acc[0][1][0], acc[0][1][1], acc[0][1][2], acc[0][1][3],
                         af0[0], af0[1], af0[2], af0[3], bf0[2], bf0[3]);
                mma16816(acc[0][2][0], acc[0][2][1], acc[0][2][2], acc[0][2][3],
                         af0[0], af0[1], af0[2], af0[3], bf1[0], bf1[1]);
                mma16816(acc[0][3][0], acc[0][3][1], acc[0][3][2], acc[0][3][3],
                         af0[0], af0[1], af0[2], af0[3], bf1[2], bf1[3]);
                mma16816(acc[1][0][0], acc[1][0][1], acc[1][0][2], acc[1][0][3],
                         af1[0], af1[1], af1[2], af1[3], bf0[0], bf0[1]);
                mma16816(acc[1][1][0], acc[1][1][1], acc[1][1][2], acc[1][1][3],
                         af1[0], af1[1], af1[2], af1[3], bf0[2], bf0[3]);
                mma16816(acc[1][2][0], acc[1][2][1], acc[1][2][2], acc[1][2][3],
                         af1[0], af1[1], af1[2], af1[3], bf1[0], bf1[1]);
                mma16816(acc[1][3][0], acc[1][3][1], acc[1][3][2], acc[1][3][3],
                         af1[0], af1[1], af1[2], af1[3], bf1[2], bf1[3]);
            }

            asm volatile("bar.sync 1, 256;" ::: "memory");
            if (tid == 0) mbar_arrive(buf ? mbE1 : mbE0);

            // epilogue: dist = n_j - 2*acc ; per-thread top-2 per row-slot
            const int jg0 = tile * 128 + hb * 64 + wn * 32 + (l & 3) * 2;
#pragma unroll
            for (int sn = 0; sn < 4; sn++) {
                const int j0 = jg0 + sn * 8;
                const float2 nn = *(const float2*)(g_norms + j0);
#pragma unroll
                for (int sm = 0; sm < 2; sm++)
#pragma unroll
                    for (int rh = 0; rh < 2; rh++) {
                        const int slot = sm * 2 + rh;
                        float d0 = fmaf(-2.f, acc[sm][sn][rh * 2 + 0], nn.x);
                        float d1 = fmaf(-2.f, acc[sm][sn][rh * 2 + 1], nn.y);
                        if (d0 < v1[slot]) { v2[slot] = v1[slot]; v1[slot] = d0; i1[slot] = j0; }
                        else if (d0 < v2[slot]) v2[slot] = d0;
                        if (d1 < v1[slot]) { v2[slot] = v1[slot]; v1[slot] = d1; i1[slot] = j0 + 1; }
                        else if (d1 < v2[slot]) v2[slot] = d1;
                    }
            }
        }

        // stash per-thread top-2 into smem (reuse A region; producer is done)
        __syncthreads();
        {
            float* sv1 = (float*)(s0 + SM_A);
            int*   si1 = (int*)(s0 + SM_A + 4096);
            float* sv2 = (float*)(s0 + SM_A + 8192);
            const int cidx = wn * 4 + (l & 3);
#pragma unroll
            for (int sm = 0; sm < 2; sm++)
#pragma unroll
                for (int rh = 0; rh < 2; rh++) {
                    const int slot = sm * 2 + rh;
                    const int row = wm * 32 + sm * 16 + rh * 8 + (l >> 2);
                    sv1[row * 8 + cidx] = v1[slot];
                    si1[row * 8 + cidx] = i1[slot];
                    sv2[row * 8 + cidx] = v2[slot];
                }
        }
        asm volatile("bar.sync 1, 256;" ::: "memory");

        if (tid < 128) {
            float* sv1 = (float*)(s0 + SM_A);
            int*   si1 = (int*)(s0 + SM_A + 4096);
            float* sv2 = (float*)(s0 + SM_A + 8192);
            float b1 = CUDART_INF_F, b2 = CUDART_INF_F; int bi = 0;
#pragma unroll
            for (int u = 0; u < 8; u++) {
                float e1 = sv1[tid * 8 + u];
                int   ei = si1[tid * 8 + u];
                float e2 = sv2[tid * 8 + u];
                if (e1 < b1 || (e1 == b1 && ei < bi)) {
                    b2 = fminf(b1, e2); b1 = e1; bi = ei;
                } else {
                    b2 = fminf(b2, e1);
                }
            }
            const int grow = blockIdx.x * 128 + tid;
            g_idx[grow] = bi;
            if (b2 - b1 <= MARGIN) {
                int pos = atomicAdd(&g_nflag, 1);
                if (pos < NS) g_flag[pos] = grow;
            }
        }
    }
}

// ------------------------------------------ exact fp32 rescue for tight rows
__global__ void k_rescue(const float* __restrict__ X, const float* __restrict__ C) {
    __shared__ float xs[DD];
    __shared__ float bv[128];
    __shared__ int   bix[128];
    const int n = g_nflag;
    for (int idx = blockIdx.x; idx < n && idx < NS; idx += gridDim.x) {
        const int row = g_flag[idx];
        if (threadIdx.x < DD) xs[threadIdx.x] = X[(size_t)row * DD + threadIdx.x];
        __syncthreads();
        float best = CUDART_INF_F; int bj = 0;
        for (int j = threadIdx.x; j < NC; j += 128) {
            float dot = 0.f;
#pragma unroll 8
            for (int d = 0; d < DD; d++)
                dot = fmaf(xs[d], C[(size_t)d * NC + j], dot);
            float v = fmaf(-2.f, dot, g_norms[j]);
            if (v < best) { best = v; bj = j; }
        }
        bv[threadIdx.x] = best; bix[threadIdx.x] = bj;
        __syncthreads();
        if (threadIdx.x == 0) {
            float b = bv[0]; int bi = bix[0];
            for (int u = 1; u < 128; u++) {
                float v = bv[u]; int ix = bix[u];
                if (v < b || (v == b && ix < bi)) { b = v; bi = ix; }
            }
            g_idx[row] = bi;
        }
        __syncthreads();
    }
}

// ------------------------------------- gather + straight-through + loss parts
__global__ void k_gather(const float* __restrict__ X, const float* __restrict__ C,
                         float* __restrict__ out) {
    int t = blockIdx.x * 256 + threadIdx.x;
    int i = t >> 7;
    int d = t & 127;
    int j = g_idx[i];
    float x = X[t];
    float q = C[(size_t)d * NC + j];
    out[t] = x + (q - x);
    float diff = q - x;
    float v = diff * diff;
#pragma unroll
    for (int off = 16; off > 0; off >>= 1)
        v += __shfl_down_sync(0xffffffffu, v, off);
    __shared__ float ws[8];
    int lane = threadIdx.x & 31, w = threadIdx.x >> 5;
    if (lane == 0) ws[w] = v;
    __syncthreads();
    if (threadIdx.x == 0) {
        double s = 0.0;
        for (int k = 0; k < 8; k++) s += (double)ws[k];
        g_partial[blockIdx.x] = s;
    }
}

__global__ void k_loss(float* __restrict__ out, int loss_pos) {
    __shared__ double sm[256];
    double s = 0.0;
    for (int k = threadIdx.x; k < NBLK; k += 256) s += g_partial[k];
    sm[threadIdx.x] = s;
    __syncthreads();
    for (int off = 128; off > 0; off >>= 1) {
        if (threadIdx.x < off) sm[threadIdx.x] += sm[threadIdx.x + off];
        __syncthreads();
    }
    if (threadIdx.x == 0 && loss_pos >= 0)
        out[loss_pos] = (float)(1.25 * sm[0] / (double)NOUT);
}

// ---------------------------------------------------------------------- entry
extern "C" void kernel_launch(void* const* d_in, const int* in_sizes, int n_in,
                              void* d_out, int out_size) {
    const float* X = (const float*)d_in[0];
    const float* C = (const float*)d_in[1];
    if (n_in >= 2 && in_sizes[0] == DD * NC && in_sizes[1] == NOUT) {
        const float* tmp = X; X = C; C = tmp;
    }
    float* out = (float*)d_out;

    static int smem_set = 0;
    if (!smem_set) {
        cudaFuncSetAttribute(k_argmin, cudaFuncAttributeMaxDynamicSharedMemorySize,
                             SMEM_REQ);
        smem_set = 1;
    }

    k_norms<<<(NT * 128 + 255) / 256, 256>>>(C);
    k_prep_x<<<NOUT / 256, 256>>>(X);
    k_prep_c<<<(NT * 128 * 128) / 256, 256>>>(C);
    k_argmin<<<128, 288, SMEM_REQ>>>();
    k_rescue<<<128, 128>>>(X, C);
    k_gather<<<NBLK, 256>>>(X, C, out);

    int loss_pos = (out_size > NOUT) ? (out_size - 1) : -1;
    k_loss<<<1, 256>>>(out, loss_pos);
}